// round 16
// baseline (speedup 1.0000x reference)
#include <cuda_runtime.h>
#include <cuda_fp16.h>
#include <math.h>
#include <stdint.h>

#define NN 50000
#define EE 800000
#define DIN 128
#define DH 64
#define DOUT 16
#define CAP 64
#define EBLK ((EE + 255) / 256)     // 3125

typedef unsigned long long u64;

// Scratch (device globals; no allocation allowed)
__device__ __align__(256) float g_t[NN * DH];        // ping (fp32)
__device__ __align__(256) float g_h[NN * DH];        // pong (fp32)
__device__ float g_dinv[NN];
__device__ int g_cnt[NN];
__device__ __align__(256) int g_bin[NN * CAP];       // binned adjacency (src ids)

#define ADD2(acc, a, b) asm("add.rn.f32x2 %0, %1, %2;" : "=l"(acc) : "l"(a), "l"(b))
#define FMA2(acc, a, b, c) asm("fma.rn.f32x2 %0, %1, %2, %3;" : "=l"(acc) : "l"(a), "l"(b), "l"(c))
#define PACK2(out, f) asm("mov.b64 %0, {%1, %1};" : "=l"(out) : "r"(__float_as_int(f)))

// ---------------------------------------------------------------- preprocessing
__global__ void k_bin(const int* __restrict__ src, const int* __restrict__ dst) {
    int i = blockIdx.x * blockDim.x + threadIdx.x;
    if (i < EE) {
        int d = dst[i];
        int pos = atomicAdd(&g_cnt[d], 1);
        if (pos < CAP) g_bin[(d << 6) + pos] = src[i];
    }
}

__global__ void k_dinv() {
    int i = blockIdx.x * blockDim.x + threadIdx.x;
    if (i < NN) g_dinv[i] = rsqrtf((float)(g_cnt[i] + 1));
}

// ---------------------------------------------------------------- mma helper
__device__ __forceinline__ void mma16816(float* d, uint32_t a0, uint32_t a1,
                                         uint32_t a2, uint32_t a3, uint32_t b0,
                                         uint32_t b1) {
    asm volatile(
        "mma.sync.aligned.m16n8k16.row.col.f32.f16.f16.f32 "
        "{%0,%1,%2,%3}, {%4,%5,%6,%7}, {%8,%9}, {%0,%1,%2,%3};\n"
        : "+f"(d[0]), "+f"(d[1]), "+f"(d[2]), "+f"(d[3])
        : "r"(a0), "r"(a1), "r"(a2), "r"(a3), "r"(b0), "r"(b1));
}

// 256-thread tile compute (gemm0 only): 8 warps, each 16 rows x 64 cols
template <int K, int LDA, int LDB, bool SCALE>
__device__ __forceinline__ void gemm_tile_compute(const __half* sA, const __half* sB,
                                                  float* C, int base) {
    int tid = threadIdx.x;
    int warp = tid >> 5, lane = tid & 31;
    int grp = lane >> 2, tig = lane & 3;
    int rowA = warp * 16 + grp;
    float acc[8][4];
#pragma unroll
    for (int j = 0; j < 8; j++)
#pragma unroll
        for (int q = 0; q < 4; q++) acc[j][q] = 0.f;

#pragma unroll
    for (int kc = 0; kc < K; kc += 16) {
        uint32_t a0 = *(const uint32_t*)(sA + rowA * LDA + kc + 2 * tig);
        uint32_t a1 = *(const uint32_t*)(sA + (rowA + 8) * LDA + kc + 2 * tig);
        uint32_t a2 = *(const uint32_t*)(sA + rowA * LDA + kc + 2 * tig + 8);
        uint32_t a3 = *(const uint32_t*)(sA + (rowA + 8) * LDA + kc + 2 * tig + 8);
#pragma unroll
        for (int j = 0; j < 8; j++) {
            uint32_t b0 = *(const uint32_t*)(sB + (j * 8 + grp) * LDB + kc + 2 * tig);
            uint32_t b1 = *(const uint32_t*)(sB + (j * 8 + grp) * LDB + kc + 2 * tig + 8);
            mma16816(acc[j], a0, a1, a2, a3, b0, b1);
        }
    }
    int r0 = base + rowA, r1 = r0 + 8;
    float s0 = 1.f, s1 = 1.f;
    if (SCALE) {
        if (r0 < NN) s0 = g_dinv[r0];
        if (r1 < NN) s1 = g_dinv[r1];
    }
#pragma unroll
    for (int j = 0; j < 8; j++) {
        int col = j * 8 + 2 * tig;
        if (r0 < NN)
            *(float2*)(C + (size_t)r0 * DH + col) = make_float2(acc[j][0] * s0, acc[j][1] * s0);
        if (r1 < NN)
            *(float2*)(C + (size_t)r1 * DH + col) = make_float2(acc[j][2] * s1, acc[j][3] * s1);
    }
}

// GEMM0: fp32 x and fp32 W0 (host inputs); no row scale; trigger after stores
__global__ void k_gemm0(const float* __restrict__ A, const float* __restrict__ W,
                        float* __restrict__ C) {
    constexpr int K = DIN, LDA = K + 8, LDB = K + 8;
    extern __shared__ __half sm[];
    __half* sA = sm;
    __half* sB = sm + 128 * LDA;
    int tid = threadIdx.x;
    int base = blockIdx.x * 128;

    for (int i = tid; i < K * 64; i += 256) {
        int k = i >> 6, n = i & 63;
        sB[n * LDB + k] = __float2half_rn(W[i]);
    }
    for (int i = tid; i < 128 * (K / 4); i += 256) {
        int r = i / (K / 4), c = i % (K / 4);
        float4 v = make_float4(0.f, 0.f, 0.f, 0.f);
        if (base + r < NN) v = *(const float4*)(A + (size_t)(base + r) * K + c * 4);
        __half2* p = (__half2*)(sA + r * LDA + c * 4);
        p[0] = __floats2half2_rn(v.x, v.y);
        p[1] = __floats2half2_rn(v.z, v.w);
    }
    __syncthreads();
    gemm_tile_compute<K, LDA, LDB, false>(sA, sB, C, base);
    cudaTriggerProgrammaticLaunchCompletion();  // after output stores
}

// ------------------------------------------------------- agg bodies (unchanged math)
__device__ __forceinline__ float2 agg_node_slow(const float* __restrict__ hinf, int node,
                                                int lane, float2 bb) {
    const u64* hp = (const u64*)hinf;
    float dd = g_dinv[node];
    int beg = node << 6;
    int end = beg + g_cnt[node];
    float2 hv = *(const float2*)(hinf + (size_t)node * DH + 2 * lane);
    u64 acc;
    {
        float2 t = make_float2(hv.x * dd * dd, hv.y * dd * dd);
        acc = *(u64*)&t;
    }
    int k = beg;
    for (; k + 4 <= end; k += 4) {
        int4 c4 = *(const int4*)(g_bin + k);
        float n0 = g_dinv[c4.x] * dd, n1 = g_dinv[c4.y] * dd;
        float n2 = g_dinv[c4.z] * dd, n3 = g_dinv[c4.w] * dd;
        u64 h0 = hp[(size_t)c4.x * 32 + lane];
        u64 h1 = hp[(size_t)c4.y * 32 + lane];
        u64 h2 = hp[(size_t)c4.z * 32 + lane];
        u64 h3 = hp[(size_t)c4.w * 32 + lane];
        u64 p0, p1, p2, p3;
        PACK2(p0, n0); PACK2(p1, n1); PACK2(p2, n2); PACK2(p3, n3);
        FMA2(acc, h0, p0, acc);
        FMA2(acc, h1, p1, acc);
        FMA2(acc, h2, p2, acc);
        FMA2(acc, h3, p3, acc);
    }
    for (; k < end; k++) {
        int j = g_bin[k];
        float n = g_dinv[j] * dd;
        u64 h = hp[(size_t)j * 32 + lane];
        u64 p;
        PACK2(p, n);
        FMA2(acc, h, p, acc);
    }
    float2 a = *(float2*)&acc;
    a.x += bb.x;
    a.y += bb.y;
    a.x = (a.x > 0.f) ? a.x : expm1f(a.x);
    a.y = (a.y > 0.f) ? a.y : expm1f(a.y);
    return a;
}

__device__ __forceinline__ float2 agg_node_fast(const float* __restrict__ hinf, int node,
                                                int lane, float2 bb) {
    const u64* hp = (const u64*)hinf;
    float dd = g_dinv[node];
    int beg = node << 6;
    int end = beg + g_cnt[node];
    u64 acc = hp[(size_t)node * 32 + lane];
    int k = beg;
    for (; k + 4 <= end; k += 4) {
        int4 c4 = *(const int4*)(g_bin + k);
        u64 h0 = hp[(size_t)c4.x * 32 + lane];
        u64 h1 = hp[(size_t)c4.y * 32 + lane];
        u64 h2 = hp[(size_t)c4.z * 32 + lane];
        u64 h3 = hp[(size_t)c4.w * 32 + lane];
        ADD2(acc, acc, h0);
        ADD2(acc, acc, h1);
        ADD2(acc, acc, h2);
        ADD2(acc, acc, h3);
    }
    for (; k < end; k++) {
        int j = g_bin[k];
        u64 h = hp[(size_t)j * 32 + lane];
        ADD2(acc, acc, h);
    }
    float2 a = *(float2*)&acc;
    a.x = fmaf(a.x, dd, bb.x);
    a.y = fmaf(a.y, dd, bb.y);
    a.x = (a.x > 0.f) ? a.x : expm1f(a.x);
    a.y = (a.y > 0.f) ? a.y : expm1f(a.y);
    return a;
}

// ------------------------------------------------------- FUSED agg + GEMM (512 threads)
// 16 warps: agg 8 nodes each -> sA fp16 tile -> 128x64 HMMA (warp-pairs split N)
template <bool FAST>
__global__ void __launch_bounds__(512) k_agg_gemm(
    const float* __restrict__ hin, const float* __restrict__ W,
    float* __restrict__ C, const float* __restrict__ bias) {
    constexpr int K = DH, LDA = K + 8, LDB = K + 8;
    extern __shared__ __half sm[];
    __half* sA = sm;                 // 128 x 72
    __half* sB = sm + 128 * LDA;     // 64 x 72
    int tid = threadIdx.x;
    int warp = tid >> 5, lane = tid & 31;
    int base = blockIdx.x * 128;

    // prologue: W is a host input — safe before grid sync
    for (int i = tid; i < K * 64; i += 512) {
        int k = i >> 6, n = i & 63;
        sB[n * LDB + k] = __float2half_rn(W[i]);
    }
    float2 bb = ((const float2*)bias)[lane];

    cudaGridDependencySynchronize();  // hin written by predecessor

    // agg phase: warp handles 8 nodes, writes ELU'd rows into sA (fp16)
    for (int t = 0; t < 8; t++) {
        int local = warp * 8 + t;
        int node = base + local;
        float2 a = make_float2(0.f, 0.f);
        if (node < NN)
            a = FAST ? agg_node_fast(hin, node, lane, bb)
                     : agg_node_slow(hin, node, lane, bb);
        *(__half2*)(sA + local * LDA + 2 * lane) = __floats2half2_rn(a.x, a.y);
    }
    __syncthreads();

    // GEMM tile: warp-pair covers 16 rows; warp>>3 selects N half
    {
        int grp = lane >> 2, tig = lane & 3;
        int rowA = (warp & 7) * 16 + grp;
        int jofs = (warp >> 3) * 4;  // 0 or 4
        float acc[4][4];
#pragma unroll
        for (int j = 0; j < 4; j++)
#pragma unroll
            for (int q = 0; q < 4; q++) acc[j][q] = 0.f;

#pragma unroll
        for (int kc = 0; kc < K; kc += 16) {
            uint32_t a0 = *(const uint32_t*)(sA + rowA * LDA + kc + 2 * tig);
            uint32_t a1 = *(const uint32_t*)(sA + (rowA + 8) * LDA + kc + 2 * tig);
            uint32_t a2 = *(const uint32_t*)(sA + rowA * LDA + kc + 2 * tig + 8);
            uint32_t a3 = *(const uint32_t*)(sA + (rowA + 8) * LDA + kc + 2 * tig + 8);
#pragma unroll
            for (int jj = 0; jj < 4; jj++) {
                int j = jofs + jj;
                uint32_t b0 = *(const uint32_t*)(sB + (j * 8 + grp) * LDB + kc + 2 * tig);
                uint32_t b1 = *(const uint32_t*)(sB + (j * 8 + grp) * LDB + kc + 2 * tig + 8);
                mma16816(acc[jj], a0, a1, a2, a3, b0, b1);
            }
        }
        int r0 = base + rowA, r1 = r0 + 8;
        float s0 = (r0 < NN) ? g_dinv[r0] : 1.f;   // pre-scale rows for next fast agg
        float s1 = (r1 < NN) ? g_dinv[r1] : 1.f;
#pragma unroll
        for (int jj = 0; jj < 4; jj++) {
            int col = (jofs + jj) * 8 + 2 * tig;
            if (r0 < NN)
                *(float2*)(C + (size_t)r0 * DH + col) =
                    make_float2(acc[jj][0] * s0, acc[jj][1] * s0);
            if (r1 < NN)
                *(float2*)(C + (size_t)r1 * DH + col) =
                    make_float2(acc[jj][2] * s1, acc[jj][3] * s1);
        }
    }
    cudaTriggerProgrammaticLaunchCompletion();  // after output stores
}

// ------------------------------------------------------- final agg + FC + softmax
__global__ void k_agg_fc(const float* __restrict__ hin, const float* __restrict__ bias,
                         const float* __restrict__ fw, const float* __restrict__ fb,
                         float* __restrict__ out) {
    __shared__ float sW[DH * DOUT];
    __shared__ float sh[8][DH];
    for (int i = threadIdx.x; i < DH * DOUT; i += 256) sW[i] = fw[i];  // input
    __syncthreads();
    int warp = threadIdx.x >> 5, lane = threadIdx.x & 31;
    int node = blockIdx.x * 8 + warp;
    if (node >= NN) return;
    float2 bb = ((const float2*)bias)[lane];
    cudaGridDependencySynchronize();  // hin from fused K2
    float2 a = agg_node_fast(hin, node, lane, bb);
    sh[warp][2 * lane] = a.x;
    sh[warp][2 * lane + 1] = a.y;
    __syncwarp();
    float v = 0.f;
    if (lane < DOUT) {
        v = fb[lane];
#pragma unroll
        for (int kk = 0; kk < DH; kk++) v = fmaf(sh[warp][kk], sW[kk * DOUT + lane], v);
    }
    float m = v;
#pragma unroll
    for (int o = 8; o; o >>= 1) m = fmaxf(m, __shfl_xor_sync(0xffffffffu, m, o, 16));
    float e = (lane < DOUT) ? expf(v - m) : 0.f;
    float s = e;
#pragma unroll
    for (int o = 8; o; o >>= 1) s += __shfl_xor_sync(0xffffffffu, s, o, 16);
    if (lane < DOUT) out[(size_t)node * DOUT + lane] = e / s;
}

// ---------------------------------------------------------------- launch
template <typename... Args>
static void launch_pdl(void (*kern)(Args...), dim3 grid, dim3 block, int smem,
                       Args... args) {
    cudaLaunchConfig_t cfg = {};
    cfg.gridDim = grid;
    cfg.blockDim = block;
    cfg.dynamicSmemBytes = (size_t)smem;
    cfg.stream = 0;
    cudaLaunchAttribute attr[1];
    attr[0].id = cudaLaunchAttributeProgrammaticStreamSerialization;
    attr[0].val.programmaticStreamSerializationAllowed = 1;
    cfg.attrs = attr;
    cfg.numAttrs = 1;
    cudaLaunchKernelEx(&cfg, kern, args...);
}

extern "C" void kernel_launch(void* const* d_in, const int* in_sizes, int n_in,
                              void* d_out, int out_size) {
    const float* x = (const float*)d_in[0];
    const int* ei = (const int*)d_in[1];
    const float* w0 = (const float*)d_in[2];
    const float* b0 = (const float*)d_in[3];
    const float* w1 = (const float*)d_in[4];
    const float* b1 = (const float*)d_in[5];
    const float* w2 = (const float*)d_in[6];
    const float* b2 = (const float*)d_in[7];
    const float* fw = (const float*)d_in[8];
    const float* fb = (const float*)d_in[9];
    float* out = (float*)d_out;
    const int* src = ei;
    const int* dst = ei + EE;

    float *p_t, *p_h;
    int* p_cnt;
    cudaGetSymbolAddress((void**)&p_t, g_t);
    cudaGetSymbolAddress((void**)&p_h, g_h);
    cudaGetSymbolAddress((void**)&p_cnt, g_cnt);

    const int smem128 = (128 * (DIN + 8) + 64 * (DIN + 8)) * 2;  // 52224 B
    const int smemF = (128 * (DH + 8) + 64 * (DH + 8)) * 2;      // 27648 B

    static cudaStream_t s2 = nullptr;
    static cudaEvent_t evFork = nullptr, evJoin = nullptr;
    if (!s2) {
        cudaStreamCreateWithFlags(&s2, cudaStreamNonBlocking);
        cudaEventCreateWithFlags(&evFork, cudaEventDisableTiming);
        cudaEventCreateWithFlags(&evJoin, cudaEventDisableTiming);
        cudaFuncSetAttribute(k_gemm0, cudaFuncAttributeMaxDynamicSharedMemorySize, smem128);
        cudaFuncSetAttribute(k_agg_gemm<false>, cudaFuncAttributeMaxDynamicSharedMemorySize, smemF);
        cudaFuncSetAttribute(k_agg_gemm<true>, cudaFuncAttributeMaxDynamicSharedMemorySize, smemF);
    }

    const int tile_grid = (NN + 127) / 128;   // 391

    // fork: binned adjacency on s2, GEMM0 on main stream
    cudaEventRecord(evFork, 0);
    cudaStreamWaitEvent(s2, evFork, 0);
    cudaMemsetAsync(p_cnt, 0, NN * sizeof(int), s2);
    k_bin<<<EBLK, 256, 0, s2>>>(src, dst);
    k_dinv<<<(NN + 255) / 256, 256, 0, s2>>>();
    cudaEventRecord(evJoin, s2);

    k_gemm0<<<tile_grid, 256, smem128>>>(x, w0, p_t);

    cudaStreamWaitEvent(0, evJoin, 0);

    // fused tail: [agg0(slow)+W1 gemm] -> [agg1(fast)+W2 gemm] -> [agg2(fast)+FC+softmax]
    launch_pdl(k_agg_gemm<false>, dim3(tile_grid), dim3(512), smemF,
               (const float*)p_t, w1, (float*)p_h, b0);
    launch_pdl(k_agg_gemm<true>, dim3(tile_grid), dim3(512), smemF,
               (const float*)p_h, w2, (float*)p_t, b1);
    launch_pdl(k_agg_fc, dim3((NN + 7) / 8), dim3(256), 0,
               (const float*)p_t, b2, fw, fb, out);
}

// round 17
// speedup vs baseline: 1.1175x; 1.1175x over previous
#include <cuda_runtime.h>
#include <cuda_fp16.h>
#include <math.h>
#include <stdint.h>

#define NN 50000
#define EE 800000
#define DIN 128
#define DH 64
#define DOUT 16
#define CAP 64
#define EBLK ((EE + 255) / 256)     // 3125

typedef unsigned long long u64;

// Scratch (device globals; no allocation allowed).
// Row NN of g_t/g_h is a permanent zero row (never written); g_dinv[NN]=0, g_cnt[NN]=0.
__device__ __align__(256) float g_t[(NN + 1) * DH];
__device__ __align__(256) float g_h[(NN + 1) * DH];
__device__ float g_dinv[NN + 1];
__device__ int g_cnt[NN + 1];
__device__ __align__(256) int g_bin[NN * CAP];

#define ADD2(acc, a, b) asm("add.rn.f32x2 %0, %1, %2;" : "=l"(acc) : "l"(a), "l"(b))
#define FMA2(acc, a, b, c) asm("fma.rn.f32x2 %0, %1, %2, %3;" : "=l"(acc) : "l"(a), "l"(b), "l"(c))
#define PACK2(out, f) asm("mov.b64 %0, {%1, %1};" : "=l"(out) : "r"(__float_as_int(f)))

// ---------------------------------------------------------------- preprocessing
__global__ void k_bin(const int* __restrict__ src, const int* __restrict__ dst) {
    int i = blockIdx.x * blockDim.x + threadIdx.x;
    if (i < EE) {
        int d = dst[i];
        int pos = atomicAdd(&g_cnt[d], 1);
        if (pos < CAP) g_bin[(d << 6) + pos] = src[i];
    }
}

// dinv + pad each bin to a multiple of 4 with dummy index NN (zero row)
__global__ void k_dinv() {
    int i = blockIdx.x * blockDim.x + threadIdx.x;
    if (i < NN) {
        int c = g_cnt[i];
        g_dinv[i] = rsqrtf((float)(c + 1));
        if (c > CAP) c = CAP;
        int r = (c + 3) & ~3;
        if (r > CAP) r = CAP;
        for (int k = c; k < r; k++) g_bin[(i << 6) + k] = NN;
    }
}

// ---------------------------------------------------------------- tensor-core GEMM
__device__ __forceinline__ void mma16816(float* d, uint32_t a0, uint32_t a1,
                                         uint32_t a2, uint32_t a3, uint32_t b0,
                                         uint32_t b1) {
    asm volatile(
        "mma.sync.aligned.m16n8k16.row.col.f32.f16.f16.f32 "
        "{%0,%1,%2,%3}, {%4,%5,%6,%7}, {%8,%9}, {%0,%1,%2,%3};\n"
        : "+f"(d[0]), "+f"(d[1]), "+f"(d[2]), "+f"(d[3])
        : "r"(a0), "r"(a1), "r"(a2), "r"(a3), "r"(b0), "r"(b1));
}

template <int K, int LDA, int LDB, bool SCALE>
__device__ __forceinline__ void gemm_tile_compute(const __half* sA, const __half* sB,
                                                  float* C, int base) {
    int tid = threadIdx.x;
    int warp = tid >> 5, lane = tid & 31;
    int grp = lane >> 2, tig = lane & 3;
    int rowA = warp * 16 + grp;
    float acc[8][4];
#pragma unroll
    for (int j = 0; j < 8; j++)
#pragma unroll
        for (int q = 0; q < 4; q++) acc[j][q] = 0.f;

#pragma unroll
    for (int kc = 0; kc < K; kc += 16) {
        uint32_t a0 = *(const uint32_t*)(sA + rowA * LDA + kc + 2 * tig);
        uint32_t a1 = *(const uint32_t*)(sA + (rowA + 8) * LDA + kc + 2 * tig);
        uint32_t a2 = *(const uint32_t*)(sA + rowA * LDA + kc + 2 * tig + 8);
        uint32_t a3 = *(const uint32_t*)(sA + (rowA + 8) * LDA + kc + 2 * tig + 8);
#pragma unroll
        for (int j = 0; j < 8; j++) {
            uint32_t b0 = *(const uint32_t*)(sB + (j * 8 + grp) * LDB + kc + 2 * tig);
            uint32_t b1 = *(const uint32_t*)(sB + (j * 8 + grp) * LDB + kc + 2 * tig + 8);
            mma16816(acc[j], a0, a1, a2, a3, b0, b1);
        }
    }
    int r0 = base + rowA, r1 = r0 + 8;
    float s0 = 1.f, s1 = 1.f;
    if (SCALE) {
        if (r0 < NN) s0 = g_dinv[r0];
        if (r1 < NN) s1 = g_dinv[r1];
    }
#pragma unroll
    for (int j = 0; j < 8; j++) {
        int col = j * 8 + 2 * tig;
        if (r0 < NN)
            *(float2*)(C + (size_t)r0 * DH + col) = make_float2(acc[j][0] * s0, acc[j][1] * s0);
        if (r1 < NN)
            *(float2*)(C + (size_t)r1 * DH + col) = make_float2(acc[j][2] * s1, acc[j][3] * s1);
    }
}

// GEMM0: fp32 x, fp32 W0 (host inputs); trigger after stores
__global__ void k_gemm0(const float* __restrict__ A, const float* __restrict__ W,
                        float* __restrict__ C) {
    constexpr int K = DIN, LDA = K + 8, LDB = K + 8;
    extern __shared__ __half sm[];
    __half* sA = sm;
    __half* sB = sm + 128 * LDA;
    int tid = threadIdx.x;
    int base = blockIdx.x * 128;

    for (int i = tid; i < K * 64; i += 256) {
        int k = i >> 6, n = i & 63;
        sB[n * LDB + k] = __float2half_rn(W[i]);
    }
    for (int i = tid; i < 128 * (K / 4); i += 256) {
        int r = i / (K / 4), c = i % (K / 4);
        float4 v = make_float4(0.f, 0.f, 0.f, 0.f);
        if (base + r < NN) v = *(const float4*)(A + (size_t)(base + r) * K + c * 4);
        __half2* p = (__half2*)(sA + r * LDA + c * 4);
        p[0] = __floats2half2_rn(v.x, v.y);
        p[1] = __floats2half2_rn(v.z, v.w);
    }
    __syncthreads();
    gemm_tile_compute<K, LDA, LDB, false>(sA, sB, C, base);
    cudaTriggerProgrammaticLaunchCompletion();
}

// GEMM 1/2: fp32 A (grid-dependent), fp32 W (input); row-scale by dinv
__global__ void k_gemm64(const float* __restrict__ A, const float* __restrict__ W,
                         float* __restrict__ C) {
    constexpr int K = DH, LDA = K + 8, LDB = K + 8;
    extern __shared__ __half sm[];
    __half* sA = sm;
    __half* sB = sm + 128 * LDA;
    int tid = threadIdx.x;
    int base = blockIdx.x * 128;

    for (int i = tid; i < K * 64; i += 256) {
        int k = i >> 6, n = i & 63;
        sB[n * LDB + k] = __float2half_rn(W[i]);
    }
    cudaGridDependencySynchronize();
    for (int i = tid; i < 128 * (K / 4); i += 256) {
        int r = i / (K / 4), c = i % (K / 4);
        float4 v = make_float4(0.f, 0.f, 0.f, 0.f);
        if (base + r < NN) v = *(const float4*)(A + (size_t)(base + r) * K + c * 4);
        __half2* p = (__half2*)(sA + r * LDA + c * 4);
        p[0] = __floats2half2_rn(v.x, v.y);
        p[1] = __floats2half2_rn(v.z, v.w);
    }
    __syncthreads();
    gemm_tile_compute<K, LDA, LDB, true>(sA, sB, C, base);
    cudaTriggerProgrammaticLaunchCompletion();
}

// ------------------------------------------------------- 2-node-per-warp agg bodies
// lane: g = lane>>4 selects node of pair, s = lane&15 owns floats [4s,4s+4)
// SLOW: per-edge norm (unscaled input). acc in two u64 (f32x2) regs.
__device__ __forceinline__ void agg2_slow(const float* __restrict__ hinf, int node, int s,
                                          u64& acc0, u64& acc1) {
    float dd = g_dinv[node];
    float4 hv = *(const float4*)(hinf + (size_t)node * DH + 4 * s);
    float d2 = dd * dd;
    float4 t = make_float4(hv.x * d2, hv.y * d2, hv.z * d2, hv.w * d2);
    acc0 = ((u64*)&t)[0];
    acc1 = ((u64*)&t)[1];
    int beg = node << 6;
    int cnt = g_cnt[node];
    if (cnt > CAP) cnt = CAP;
    int steps = (cnt + 3) & ~3;
    for (int k = 0;; k += 4) {
        bool act = k < steps;
        if (!__any_sync(0xffffffffu, act)) break;
        if (act) {
            int4 c4 = *(const int4*)(g_bin + beg + k);
            float n0 = g_dinv[c4.x] * dd, n1 = g_dinv[c4.y] * dd;
            float n2 = g_dinv[c4.z] * dd, n3 = g_dinv[c4.w] * dd;
            float4 v0 = *(const float4*)(hinf + (size_t)c4.x * DH + 4 * s);
            float4 v1 = *(const float4*)(hinf + (size_t)c4.y * DH + 4 * s);
            float4 v2 = *(const float4*)(hinf + (size_t)c4.z * DH + 4 * s);
            float4 v3 = *(const float4*)(hinf + (size_t)c4.w * DH + 4 * s);
            u64 p0, p1, p2, p3;
            PACK2(p0, n0); PACK2(p1, n1); PACK2(p2, n2); PACK2(p3, n3);
            FMA2(acc0, ((u64*)&v0)[0], p0, acc0); FMA2(acc1, ((u64*)&v0)[1], p0, acc1);
            FMA2(acc0, ((u64*)&v1)[0], p1, acc0); FMA2(acc1, ((u64*)&v1)[1], p1, acc1);
            FMA2(acc0, ((u64*)&v2)[0], p2, acc0); FMA2(acc1, ((u64*)&v2)[1], p2, acc1);
            FMA2(acc0, ((u64*)&v3)[0], p3, acc0); FMA2(acc1, ((u64*)&v3)[1], p3, acc1);
        }
    }
}

// FAST: input rows pre-scaled by dinv; pure adds; caller applies ×dd + bias
__device__ __forceinline__ void agg2_fast(const float* __restrict__ hinf, int node, int s,
                                          u64& acc0, u64& acc1) {
    float4 hv = *(const float4*)(hinf + (size_t)node * DH + 4 * s);
    acc0 = ((u64*)&hv)[0];
    acc1 = ((u64*)&hv)[1];
    int beg = node << 6;
    int cnt = g_cnt[node];
    if (cnt > CAP) cnt = CAP;
    int steps = (cnt + 3) & ~3;
    for (int k = 0;; k += 4) {
        bool act = k < steps;
        if (!__any_sync(0xffffffffu, act)) break;
        if (act) {
            int4 c4 = *(const int4*)(g_bin + beg + k);
            float4 v0 = *(const float4*)(hinf + (size_t)c4.x * DH + 4 * s);
            float4 v1 = *(const float4*)(hinf + (size_t)c4.y * DH + 4 * s);
            float4 v2 = *(const float4*)(hinf + (size_t)c4.z * DH + 4 * s);
            float4 v3 = *(const float4*)(hinf + (size_t)c4.w * DH + 4 * s);
            ADD2(acc0, acc0, ((u64*)&v0)[0]); ADD2(acc1, acc1, ((u64*)&v0)[1]);
            ADD2(acc0, acc0, ((u64*)&v1)[0]); ADD2(acc1, acc1, ((u64*)&v1)[1]);
            ADD2(acc0, acc0, ((u64*)&v2)[0]); ADD2(acc1, acc1, ((u64*)&v2)[1]);
            ADD2(acc0, acc0, ((u64*)&v3)[0]); ADD2(acc1, acc1, ((u64*)&v3)[1]);
        }
    }
}

__device__ __forceinline__ float4 elu4(float4 a) {
    a.x = (a.x > 0.f) ? a.x : expm1f(a.x);
    a.y = (a.y > 0.f) ? a.y : expm1f(a.y);
    a.z = (a.z > 0.f) ? a.z : expm1f(a.z);
    a.w = (a.w > 0.f) ? a.w : expm1f(a.w);
    return a;
}

// layer 0 (slow path); block (32,8) -> 16 nodes per block
__global__ void k_agg0(const float* __restrict__ hin, float* __restrict__ hout,
                       const float* __restrict__ bias) {
    int lane = threadIdx.x, g = lane >> 4, s = lane & 15;
    int node = blockIdx.x * 16 + threadIdx.y * 2 + g;
    bool valid = node < NN;
    if (!valid) node = NN;
    float4 bbv = ((const float4*)bias)[s];
    cudaGridDependencySynchronize();
    u64 a0, a1;
    agg2_slow(hin, node, s, a0, a1);
    float4 a;
    ((u64*)&a)[0] = a0;
    ((u64*)&a)[1] = a1;
    a.x += bbv.x; a.y += bbv.y; a.z += bbv.z; a.w += bbv.w;
    a = elu4(a);
    if (valid) *(float4*)(hout + (size_t)node * DH + 4 * s) = a;
    cudaTriggerProgrammaticLaunchCompletion();
}

// layer 1 (fast path)
__global__ void k_agg(const float* __restrict__ hin, float* __restrict__ hout,
                      const float* __restrict__ bias) {
    int lane = threadIdx.x, g = lane >> 4, s = lane & 15;
    int node = blockIdx.x * 16 + threadIdx.y * 2 + g;
    bool valid = node < NN;
    if (!valid) node = NN;
    float4 bbv = ((const float4*)bias)[s];
    cudaGridDependencySynchronize();
    float dd = g_dinv[node];
    u64 a0, a1;
    agg2_fast(hin, node, s, a0, a1);
    float4 a;
    ((u64*)&a)[0] = a0;
    ((u64*)&a)[1] = a1;
    a.x = fmaf(a.x, dd, bbv.x);
    a.y = fmaf(a.y, dd, bbv.y);
    a.z = fmaf(a.z, dd, bbv.z);
    a.w = fmaf(a.w, dd, bbv.w);
    a = elu4(a);
    if (valid) *(float4*)(hout + (size_t)node * DH + 4 * s) = a;
    cudaTriggerProgrammaticLaunchCompletion();
}

// layer 2 (fast) + FC + softmax; 256 threads flat, 16 nodes per block
__global__ void k_agg_fc(const float* __restrict__ hin, const float* __restrict__ bias,
                         const float* __restrict__ fw, const float* __restrict__ fb,
                         float* __restrict__ out) {
    __shared__ float sW[DH * DOUT];
    __shared__ float sh[16][DH];
    for (int i = threadIdx.x; i < DH * DOUT; i += 256) sW[i] = fw[i];  // input
    __syncthreads();
    int warp = threadIdx.x >> 5, lane = threadIdx.x & 31;
    int g = lane >> 4, s = lane & 15;
    int local = warp * 2 + g;
    int node = blockIdx.x * 16 + local;
    bool valid = node < NN;
    if (!valid) node = NN;
    float4 bbv = ((const float4*)bias)[s];
    float fbv = fb[s];
    cudaGridDependencySynchronize();
    float dd = g_dinv[node];
    u64 a0, a1;
    agg2_fast(hin, node, s, a0, a1);
    float4 a;
    ((u64*)&a)[0] = a0;
    ((u64*)&a)[1] = a1;
    a.x = fmaf(a.x, dd, bbv.x);
    a.y = fmaf(a.y, dd, bbv.y);
    a.z = fmaf(a.z, dd, bbv.z);
    a.w = fmaf(a.w, dd, bbv.w);
    a = elu4(a);
    *(float4*)(&sh[local][4 * s]) = a;
    __syncwarp();
    float v = fbv;
#pragma unroll
    for (int kk = 0; kk < DH; kk++) v = fmaf(sh[local][kk], sW[kk * DOUT + s], v);
    float m = v;
#pragma unroll
    for (int o = 8; o; o >>= 1) m = fmaxf(m, __shfl_xor_sync(0xffffffffu, m, o, 16));
    float e = expf(v - m);
    float sum = e;
#pragma unroll
    for (int o = 8; o; o >>= 1) sum += __shfl_xor_sync(0xffffffffu, sum, o, 16);
    if (valid) out[(size_t)node * DOUT + s] = e / sum;
}

// ---------------------------------------------------------------- launch
template <typename... Args>
static void launch_pdl(void (*kern)(Args...), dim3 grid, dim3 block, int smem,
                       Args... args) {
    cudaLaunchConfig_t cfg = {};
    cfg.gridDim = grid;
    cfg.blockDim = block;
    cfg.dynamicSmemBytes = (size_t)smem;
    cfg.stream = 0;
    cudaLaunchAttribute attr[1];
    attr[0].id = cudaLaunchAttributeProgrammaticStreamSerialization;
    attr[0].val.programmaticStreamSerializationAllowed = 1;
    cfg.attrs = attr;
    cfg.numAttrs = 1;
    cudaLaunchKernelEx(&cfg, kern, args...);
}

extern "C" void kernel_launch(void* const* d_in, const int* in_sizes, int n_in,
                              void* d_out, int out_size) {
    const float* x = (const float*)d_in[0];
    const int* ei = (const int*)d_in[1];
    const float* w0 = (const float*)d_in[2];
    const float* b0 = (const float*)d_in[3];
    const float* w1 = (const float*)d_in[4];
    const float* b1 = (const float*)d_in[5];
    const float* w2 = (const float*)d_in[6];
    const float* b2 = (const float*)d_in[7];
    const float* fw = (const float*)d_in[8];
    const float* fb = (const float*)d_in[9];
    float* out = (float*)d_out;
    const int* src = ei;
    const int* dst = ei + EE;

    float *p_t, *p_h;
    int* p_cnt;
    cudaGetSymbolAddress((void**)&p_t, g_t);
    cudaGetSymbolAddress((void**)&p_h, g_h);
    cudaGetSymbolAddress((void**)&p_cnt, g_cnt);

    const int smem128 = (128 * (DIN + 8) + 64 * (DIN + 8)) * 2;  // 52224 B
    const int smem64 = (128 * (DH + 8) + 64 * (DH + 8)) * 2;     // 27648 B

    static cudaStream_t s2 = nullptr;
    static cudaEvent_t evFork = nullptr, evJoin = nullptr;
    if (!s2) {
        cudaStreamCreateWithFlags(&s2, cudaStreamNonBlocking);
        cudaEventCreateWithFlags(&evFork, cudaEventDisableTiming);
        cudaEventCreateWithFlags(&evJoin, cudaEventDisableTiming);
        cudaFuncSetAttribute(k_gemm0, cudaFuncAttributeMaxDynamicSharedMemorySize, smem128);
        cudaFuncSetAttribute(k_gemm64, cudaFuncAttributeMaxDynamicSharedMemorySize, smem64);
    }

    const int gemm_grid = (NN + 127) / 128;   // 391
    const dim3 agg_block(32, 8);
    const int agg_grid = (NN + 15) / 16;      // 3125

    // fork: binned adjacency on s2, GEMM0 on main stream
    cudaEventRecord(evFork, 0);
    cudaStreamWaitEvent(s2, evFork, 0);
    cudaMemsetAsync(p_cnt, 0, (NN + 1) * sizeof(int), s2);
    k_bin<<<EBLK, 256, 0, s2>>>(src, dst);
    k_dinv<<<(NN + 255) / 256, 256, 0, s2>>>();
    cudaEventRecord(evJoin, s2);

    k_gemm0<<<gemm_grid, 256, smem128>>>(x, w0, p_t);

    cudaStreamWaitEvent(0, evJoin, 0);

    launch_pdl(k_agg0, dim3(agg_grid), agg_block, 0,
               (const float*)p_t, (float*)p_h, b0);
    launch_pdl(k_gemm64, dim3(gemm_grid), dim3(256), smem64,
               (const float*)p_h, w1, (float*)p_t);
    launch_pdl(k_agg, dim3(agg_grid), agg_block, 0,
               (const float*)p_t, (float*)p_h, b1);
    launch_pdl(k_gemm64, dim3(gemm_grid), dim3(256), smem64,
               (const float*)p_h, w2, (float*)p_t);
    launch_pdl(k_agg_fc, dim3(agg_grid), dim3(256), 0,
               (const float*)p_t, b2, fw, fb, out);
}